// round 15
// baseline (speedup 1.0000x reference)
#include <cuda_runtime.h>
#include <cuda_fp16.h>
#include <math_constants.h>
#include <cstdint>

#define BATCH 16
#define CDIM  512
#define NPOS  4096      // 64*64
#define O3    1536      // 3*HID
#define HID   512
#define HEADS 8
#define DH    64
#define EPSV  1e-5f
#define QSCALE 0.125f   // DH^-0.5

typedef __half h16;

// ---------------- scratch (device globals; no allocations allowed) ---------
__device__ float g_mean [BATCH * NPOS];   // LN1 mean; reused as LN2 col-sum
__device__ float g_rstd [BATCH * NPOS];   // LN1 rstd; reused as LN2 col-sum2
__device__ h16   g_xt   [(size_t)BATCH * NPOS * CDIM];   // x normalized, channel-last fp16
__device__ float g_qkv  [(size_t)BATCH * O3   * NPOS];   // channel-major fp32
__device__ float g_ctx  [BATCH * HEADS * DH * DH];
__device__ float g_kmx  [BATCH * HEADS * DH];            // k row max
__device__ float g_krz  [BATCH * HEADS * DH];            // k row 1/sum
__device__ h16   g_at   [(size_t)BATCH * NPOS * HID];    // attn out, channel-last fp16
__device__ float g_outpre[(size_t)BATCH * CDIM * NPOS];  // pre-final-LN, channel-major
__device__ h16   g_wq   [O3  * CDIM];
__device__ h16   g_wo   [HID * CDIM];

// ======================= mma.sync / cp.async helpers (sm_80+) ==============
__device__ __forceinline__ uint32_t smem_to_u32(const void* p) {
    uint32_t a;
    asm("{ .reg .u64 t; cvta.to.shared.u64 t, %1; cvt.u32.u64 %0, t; }"
        : "=r"(a) : "l"(p));
    return a;
}
__device__ __forceinline__ void ldsm_x4(uint32_t& r0, uint32_t& r1,
                                        uint32_t& r2, uint32_t& r3, uint32_t addr) {
    asm volatile("ldmatrix.sync.aligned.m8n8.x4.shared.b16 {%0,%1,%2,%3}, [%4];"
        : "=r"(r0), "=r"(r1), "=r"(r2), "=r"(r3) : "r"(addr));
}
__device__ __forceinline__ void mma16816(float* d, const uint32_t* a,
                                         uint32_t b0, uint32_t b1) {
    asm volatile(
        "mma.sync.aligned.m16n8k16.row.col.f32.f16.f16.f32 "
        "{%0,%1,%2,%3},{%4,%5,%6,%7},{%8,%9},{%0,%1,%2,%3};"
        : "+f"(d[0]), "+f"(d[1]), "+f"(d[2]), "+f"(d[3])
        : "r"(a[0]), "r"(a[1]), "r"(a[2]), "r"(a[3]), "r"(b0), "r"(b1));
}
__device__ __forceinline__ void cp_async16(uint32_t saddr, const void* gaddr) {
    asm volatile("cp.async.ca.shared.global [%0], [%1], 16;"
        :: "r"(saddr), "l"(gaddr));
}
#define CP_COMMIT()  asm volatile("cp.async.commit_group;" ::: "memory")
#define CP_WAIT(N)   asm volatile("cp.async.wait_group %0;" :: "n"(N) : "memory")

// ======================= single-product fp16 tensor-core GEMM ==============
// R7 OPTIMUM: 256 thr, 4x2 warps, warp tile 32x64, 2-stage, KC=64,
// 73.7 KB dyn smem, 2 CTAs/SM. Optional LN-stat accumulation in epilogue.
// C[b, bm+r, bn+c] = sum_k W[bm+r, k] * X[b, bn+c, k]  (+ bias[bm+r])
#define KC  64
#define LDT 72                              // KC + 8 pad; row stride 144 B
#define TILE_BYTES (128 * LDT * 2)          // 18432 B per tile
#define STAGE_BYTES (2 * TILE_BYTES)        // W, X  -> 36864 B
#define GEMM_SMEM  (2 * STAGE_BYTES)        // 73728 B (2 stages)

__global__ __launch_bounds__(256, 2) void gemm_mma(
    const h16* __restrict__ W, const h16* __restrict__ X,
    float* __restrict__ C, const float* __restrict__ bias, int M_total,
    float* __restrict__ cs1, float* __restrict__ cs2)
{
    extern __shared__ char sm[];
    __shared__ float s1[128], s2[128];
    uint32_t sbase = smem_to_u32(sm);

    int tid = threadIdx.x, wid = tid >> 5, lane = tid & 31;
    int b = blockIdx.z, bm = blockIdx.y * 128, bn = blockIdx.x * 128;
    int warp_m = (wid & 3) * 32;        // 4 warps along M
    int warp_n = (wid >> 2) * 64;       // 2 warps along N

    const uint4* gW = (const uint4*)W + (size_t)bm * 64;
    const uint4* gX = (const uint4*)X + ((size_t)b * NPOS + bn) * 64;

    float acc[2][8][4];
    #pragma unroll
    for (int mt = 0; mt < 2; mt++)
        #pragma unroll
        for (int nt = 0; nt < 8; nt++)
            #pragma unroll
            for (int f = 0; f < 4; f++) acc[mt][nt][f] = 0.f;

    auto load_stage = [&](int s, int kc) {
        uint32_t ub = sbase + (uint32_t)s * STAGE_BYTES;
        #pragma unroll
        for (int l = 0; l < 4; l++) {
            int i = l * 256 + tid;
            int row = i >> 3, c8 = i & 7;
            size_t go = (size_t)row * 64 + kc * 8 + c8;
            uint32_t so = ub + (uint32_t)(row * LDT + c8 * 8) * 2;
            cp_async16(so,              gW + go);
            cp_async16(so + TILE_BYTES, gX + go);
        }
    };

    load_stage(0, 0);
    CP_COMMIT();

    for (int kc = 0; kc < 8; kc++) {
        if (kc + 1 < 8) {
            load_stage((kc + 1) & 1, kc + 1);
            CP_COMMIT();
            CP_WAIT(1);
        } else {
            CP_WAIT(0);
        }
        __syncthreads();

        uint32_t ub = sbase + (uint32_t)(kc & 1) * STAGE_BYTES;
        uint32_t uW = ub;
        uint32_t uX = ub + TILE_BYTES;

        #pragma unroll
        for (int kk = 0; kk < 4; kk++) {
            uint32_t ah[2][4];
            #pragma unroll
            for (int mt = 0; mt < 2; mt++) {
                uint32_t off = 2 * (uint32_t)((warp_m + mt * 16 + (lane & 15)) * LDT
                                              + kk * 16 + (lane >> 4) * 8);
                ldsm_x4(ah[mt][0], ah[mt][1], ah[mt][2], ah[mt][3], uW + off);
            }
            #pragma unroll
            for (int nt2 = 0; nt2 < 4; nt2++) {
                uint32_t off = 2 * (uint32_t)((warp_n + nt2 * 16 + (lane & 15)) * LDT
                                              + kk * 16 + (lane >> 4) * 8);
                uint32_t b0, b1, b2, b3;
                ldsm_x4(b0, b1, b2, b3, uX + off);
                #pragma unroll
                for (int mt = 0; mt < 2; mt++) {
                    mma16816(acc[mt][nt2 * 2 + 0], ah[mt], b0, b2);
                    mma16816(acc[mt][nt2 * 2 + 1], ah[mt], b1, b3);
                }
            }
        }
        __syncthreads();
    }

    if (cs1) {
        if (tid < 128) { s1[tid] = 0.f; s2[tid] = 0.f; }
        __syncthreads();
    }

    #pragma unroll
    for (int mt = 0; mt < 2; mt++) {
        int r0 = bm + warp_m + mt * 16 + (lane >> 2);
        float bb0 = bias ? bias[r0] : 0.f;
        float bb8 = bias ? bias[r0 + 8] : 0.f;
        #pragma unroll
        for (int nt = 0; nt < 8; nt++) {
            int col = bn + warp_n + nt * 8 + 2 * (lane & 3);
            float v00 = acc[mt][nt][0] + bb0, v01 = acc[mt][nt][1] + bb0;
            float v10 = acc[mt][nt][2] + bb8, v11 = acc[mt][nt][3] + bb8;
            *(float2*)&C[((size_t)b * M_total + r0    ) * NPOS + col] =
                make_float2(v00, v01);
            *(float2*)&C[((size_t)b * M_total + r0 + 8) * NPOS + col] =
                make_float2(v10, v11);
            if (cs1) {
                int c0 = warp_n + nt * 8 + 2 * (lane & 3);
                atomicAdd(&s1[c0],     v00 + v10);
                atomicAdd(&s1[c0 + 1], v01 + v11);
                atomicAdd(&s2[c0],     v00 * v00 + v10 * v10);
                atomicAdd(&s2[c0 + 1], v01 * v01 + v11 * v11);
            }
        }
    }
    if (cs1) {
        __syncthreads();
        if (tid < 128) {
            atomicAdd(&cs1[(size_t)b * NPOS + bn + tid], s1[tid]);
            atomicAdd(&cs2[(size_t)b * NPOS + bn + tid], s2[tid]);
        }
    }
}

// ---------------- LN stats: mean/rstd over C per (b,p) ---------------------
__global__ __launch_bounds__(256) void ln_stats_kernel(
    const float* __restrict__ in, float* __restrict__ mean, float* __restrict__ rstd)
{
    int gid = blockIdx.x * 256 + threadIdx.x;
    int b = gid >> 12, p = gid & (NPOS - 1);
    const float* ip = in + (size_t)b * CDIM * NPOS + p;
    float s = 0.f, s2 = 0.f;
    #pragma unroll 8
    for (int c = 0; c < CDIM; c++) {
        float v = ip[(size_t)c * NPOS];
        s += v; s2 += v * v;
    }
    float m = s * (1.f / CDIM);
    float var = s2 * (1.f / CDIM) - m * m;
    mean[gid] = m;
    rstd[gid] = rsqrtf(var + EPSV);
}

// ---------------- normalize + transpose to channel-last fp16 ---------------
__global__ __launch_bounds__(256) void norm_transpose_kernel(
    const float* __restrict__ x, const float* __restrict__ g,
    const float* __restrict__ mean, const float* __restrict__ rstd,
    h16* __restrict__ xt)
{
    __shared__ float t[64][65];
    int b = blockIdx.z, c0 = blockIdx.y * 64, p0 = blockIdx.x * 64;
    int tid = threadIdx.x;
    #pragma unroll
    for (int l = 0; l < 16; l++) {
        int i = l * 256 + tid;
        int c = i >> 6, p = i & 63;
        float v = x[((size_t)b * CDIM + c0 + c) * NPOS + p0 + p];
        int sp = b * NPOS + p0 + p;
        t[p][c] = (v - mean[sp]) * rstd[sp] * g[c0 + c];
    }
    __syncthreads();
    #pragma unroll
    for (int l = 0; l < 16; l++) {
        int i = l * 256 + tid;
        int p = i >> 6, c = i & 63;
        size_t o = ((size_t)b * NPOS + p0 + p) * CDIM + c0 + c;
        xt[o] = __float2half(t[p][c]);
    }
}

// ---------------- fp32 -> fp16 convert (weights) ---------------------------
__global__ __launch_bounds__(256) void conv_fp16_kernel(
    const float* __restrict__ w, h16* __restrict__ h, int n)
{
    int i = blockIdx.x * 256 + threadIdx.x;
    if (i < n) h[i] = __float2half(w[i]);
}

// ---------------- warp reductions ------------------------------------------
__device__ __forceinline__ float warp_max(float v) {
    #pragma unroll
    for (int o = 16; o > 0; o >>= 1) v = fmaxf(v, __shfl_xor_sync(0xffffffffu, v, o));
    return v;
}
__device__ __forceinline__ float warp_sum(float v) {
    #pragma unroll
    for (int o = 16; o > 0; o >>= 1) v += __shfl_xor_sync(0xffffffffu, v, o);
    return v;
}

// ---------------- k row stats: max + 1/sum(exp) over n ---------------------
__global__ __launch_bounds__(256) void kstats_kernel(
    const float* __restrict__ qkv, float* __restrict__ kmx, float* __restrict__ krz)
{
    __shared__ float red[8];
    int row = blockIdx.x;
    int i = row & (DH - 1);
    int m = (row >> 6) & (HEADS - 1);
    int b = row >> 9;
    const float* base = qkv + (size_t)b * O3 * NPOS + (size_t)(HID + m * DH + i) * NPOS;
    int t = threadIdx.x;
    int lane = t & 31, wid = t >> 5;

    float v[16];
    float mx = -CUDART_INF_F;
    #pragma unroll
    for (int u = 0; u < 16; u++) {
        v[u] = base[u * 256 + t];
        mx = fmaxf(mx, v[u]);
    }
    mx = warp_max(mx);
    if (lane == 0) red[wid] = mx;
    __syncthreads();
    mx = warp_max((lane < 8) ? red[lane] : -CUDART_INF_F);
    mx = __shfl_sync(0xffffffffu, mx, 0);

    float s = 0.f;
    #pragma unroll
    for (int u = 0; u < 16; u++) s += __expf(v[u] - mx);
    s = warp_sum(s);
    __syncthreads();
    if (lane == 0) red[wid] = s;
    __syncthreads();
    s = warp_sum((lane < 8) ? red[lane] : 0.f);
    s = __shfl_sync(0xffffffffu, s, 0);

    if (t == 0) { kmx[row] = mx; krz[row] = 1.f / s; }
}

// ---------------- zero (3 arrays in one launch) ----------------------------
__global__ __launch_bounds__(256) void zero3_kernel(
    float* __restrict__ p1, int n1, float* __restrict__ p2, int n2,
    float* __restrict__ p3, int n3)
{
    int i = blockIdx.x * 256 + threadIdx.x;
    if (i < n1) p1[i] = 0.f;
    if (i < n2) p2[i] = 0.f;
    if (i < n3) p3[i] = 0.f;
}

// -------- context[b,m,i,j] = (1/Z_i) sum_n exp(k[i,n]-mx_i) * v[j,n] -------
#define NSPLIT 4
__global__ __launch_bounds__(256) void context_kernel(
    const float* __restrict__ qkv, const float* __restrict__ kmx,
    const float* __restrict__ krz, float* __restrict__ ctx)
{
    __shared__ float Ks[64][65];
    __shared__ float Vs[64][65];
    int bm = blockIdx.x;
    int m = bm & (HEADS - 1);
    int b = bm >> 3;
    const float* kbase = qkv + (size_t)b * O3 * NPOS + (size_t)(HID     + m * DH) * NPOS;
    const float* vbase = qkv + (size_t)b * O3 * NPOS + (size_t)(2 * HID + m * DH) * NPOS;
    int tid = threadIdx.x;
    int ti = tid & 15, tj = tid >> 4;

    float acc[4][4];
    #pragma unroll
    for (int a = 0; a < 4; a++)
        #pragma unroll
        for (int c = 0; c < 4; c++) acc[a][c] = 0.f;

    int nsplit = NPOS / NSPLIT;
    int nstart = blockIdx.y * nsplit;
    for (int nc = 0; nc < nsplit; nc += 64) {
        int nb = nstart + nc;
        #pragma unroll
        for (int l = 0; l < 16; l++) {
            int idx = l * 256 + tid;
            int i = idx >> 6, nn = idx & 63;
            Ks[nn][i] = __expf(kbase[(size_t)i * NPOS + nb + nn] - kmx[bm * DH + i]);
            Vs[nn][i] = vbase[(size_t)i * NPOS + nb + nn];
        }
        __syncthreads();
        #pragma unroll 8
        for (int nn = 0; nn < 64; nn++) {
            float ka[4], vb[4];
            #pragma unroll
            for (int a = 0; a < 4; a++) ka[a] = Ks[nn][ti * 4 + a];
            #pragma unroll
            for (int c = 0; c < 4; c++) vb[c] = Vs[nn][tj * 4 + c];
            #pragma unroll
            for (int a = 0; a < 4; a++)
                #pragma unroll
                for (int c = 0; c < 4; c++) acc[a][c] += ka[a] * vb[c];
        }
        __syncthreads();
    }
    #pragma unroll
    for (int a = 0; a < 4; a++) {
        float rz = krz[bm * DH + ti * 4 + a];
        #pragma unroll
        for (int c = 0; c < 4; c++)
            atomicAdd(&ctx[(size_t)bm * DH * DH + (ti * 4 + a) * DH + (tj * 4 + c)],
                      acc[a][c] * rz);
    }
}

// -------- attn_out -> channel-last fp16, with INLINE q softmax -------------
__global__ __launch_bounds__(128) void attnout_kernel(
    const float* __restrict__ qkv, const float* __restrict__ ctx,
    h16* __restrict__ at)
{
    __shared__ float cs[DH][DH];        // 16 KB
    __shared__ float stage[128][64];    // 32 KB
    int bm = blockIdx.y;
    int m = bm & (HEADS - 1);
    int b = bm >> 3;
    const float* qbase = qkv + (size_t)b * O3 * NPOS + (size_t)(m * DH) * NPOS;
    int tid = threadIdx.x;

    #pragma unroll
    for (int l = 0; l < 32; l++)
        ((float*)cs)[l * 128 + tid] = ctx[(size_t)bm * DH * DH + l * 128 + tid];
    __syncthreads();

    int n0 = blockIdx.x * 128;
    int n = n0 + tid;

    float v[DH];
    float mx = -CUDART_INF_F;
    #pragma unroll
    for (int i = 0; i < DH; i++) {
        v[i] = qbase[(size_t)i * NPOS + n];
        mx = fmaxf(mx, v[i]);
    }
    float s = 0.f;
    #pragma unroll
    for (int i = 0; i < DH; i++) { v[i] = __expf(v[i] - mx); s += v[i]; }
    float r = QSCALE / s;

    float accj[DH];
    #pragma unroll
    for (int j = 0; j < DH; j++) accj[j] = 0.f;

    #pragma unroll 2
    for (int i = 0; i < DH; i++) {
        float qv = v[i];
        const float4* rowp = (const float4*)cs[i];
        #pragma unroll
        for (int j4 = 0; j4 < 16; j4++) {
            float4 c4 = rowp[j4];
            accj[j4 * 4 + 0] += c4.x * qv;
            accj[j4 * 4 + 1] += c4.y * qv;
            accj[j4 * 4 + 2] += c4.z * qv;
            accj[j4 * 4 + 3] += c4.w * qv;
        }
    }
    #pragma unroll
    for (int j = 0; j < DH; j++) stage[tid][(j + tid) & 63] = accj[j] * r;
    __syncthreads();

    #pragma unroll
    for (int l = 0; l < 64; l++) {
        int idx = l * 128 + tid;
        int p = idx >> 6, j = idx & 63;
        size_t o = ((size_t)b * NPOS + n0 + p) * HID + m * DH + j;
        at[o] = __float2half(stage[p][(j + p) & 63]);
    }
}

// -------- final LN: normalize-only (stats precomputed in GEMM2 epilogue) ---
__global__ __launch_bounds__(256) void chan_norm_kernel(
    const float* __restrict__ in, const float* __restrict__ g,
    const float* __restrict__ cs1, const float* __restrict__ cs2,
    float* __restrict__ out)
{
    int gid = blockIdx.x * 256 + threadIdx.x;
    int b = gid >> 12;
    int p = gid & (NPOS - 1);
    const float* ip = in  + (size_t)b * CDIM * NPOS + p;
    float*       op = out + (size_t)b * CDIM * NPOS + p;

    float mean = cs1[gid] * (1.f / CDIM);
    float var  = cs2[gid] * (1.f / CDIM) - mean * mean;
    float rstd = rsqrtf(var + EPSV);

    #pragma unroll 8
    for (int c = 0; c < CDIM; c++) {
        float v = ip[(size_t)c * NPOS];
        op[(size_t)c * NPOS] = (v - mean) * rstd * g[c];
    }
}

// ---------------- launch ---------------------------------------------------
extern "C" void kernel_launch(void* const* d_in, const int* in_sizes, int n_in,
                              void* d_out, int out_size)
{
    const float* x          = (const float*)d_in[0];
    const float* norm_g     = (const float*)d_in[1];
    const float* qkv_w      = (const float*)d_in[2];
    const float* out_w      = (const float*)d_in[3];
    const float* out_b      = (const float*)d_in[4];
    const float* out_norm_g = (const float*)d_in[5];
    float* out = (float*)d_out;

    float *mean, *rstd, *qkv, *ctx, *kmx, *krz, *outpre;
    h16 *xt, *at, *wq, *wo;
    cudaGetSymbolAddress((void**)&mean,   g_mean);
    cudaGetSymbolAddress((void**)&rstd,   g_rstd);
    cudaGetSymbolAddress((void**)&xt,     g_xt);
    cudaGetSymbolAddress((void**)&qkv,    g_qkv);
    cudaGetSymbolAddress((void**)&ctx,    g_ctx);
    cudaGetSymbolAddress((void**)&kmx,    g_kmx);
    cudaGetSymbolAddress((void**)&krz,    g_krz);
    cudaGetSymbolAddress((void**)&at,     g_at);
    cudaGetSymbolAddress((void**)&outpre, g_outpre);
    cudaGetSymbolAddress((void**)&wq,     g_wq);
    cudaGetSymbolAddress((void**)&wo,     g_wo);

    cudaFuncSetAttribute(gemm_mma, cudaFuncAttributeMaxDynamicSharedMemorySize,
                         GEMM_SMEM);

    // 1. LN1: stats + normalize-transpose -> xt fp16 (R7 path)
    ln_stats_kernel<<<BATCH * NPOS / 256, 256>>>(x, mean, rstd);
    norm_transpose_kernel<<<dim3(NPOS / 64, CDIM / 64, BATCH), 256>>>(
        x, norm_g, mean, rstd, xt);

    // 2. weight converts (single fp16)
    conv_fp16_kernel<<<(O3 * CDIM) / 256, 256>>>(qkv_w, wq, O3 * CDIM);
    conv_fp16_kernel<<<(HID * CDIM) / 256, 256>>>(out_w, wo, HID * CDIM);

    // 3. qkv GEMM (R7 optimum config, fp32 out, no stats)
    gemm_mma<<<dim3(NPOS / 128, O3 / 128, BATCH), 256, GEMM_SMEM>>>(
        wq, xt, qkv, nullptr, O3, nullptr, nullptr);

    // 4. k row stats (R7 path)
    kstats_kernel<<<BATCH * HEADS * DH, 256>>>(qkv, kmx, krz);

    // 5. zero ctx + LN2 stat accumulators (mean/rstd now free after LN1)
    int ctx_n = BATCH * HEADS * DH * DH;
    int st_n  = BATCH * NPOS;
    zero3_kernel<<<(ctx_n + 255) / 256, 256>>>(ctx, ctx_n, mean, st_n, rstd, st_n);

    // 6. context = softmax(k) @ v^T (R7 path)
    context_kernel<<<dim3(BATCH * HEADS, NSPLIT), 256>>>(qkv, kmx, krz, ctx);

    // 7. attn out (inline q softmax) -> channel-last fp16 (R7 path)
    attnout_kernel<<<dim3(NPOS / 128, BATCH * HEADS), 128>>>(qkv, ctx, at);

    // 8. out projection + bias -> outpre, WITH fused LN2 stat accumulation
    gemm_mma<<<dim3(NPOS / 128, HID / 128, BATCH), 256, GEMM_SMEM>>>(
        wo, at, outpre, out_b, HID, mean, rstd);

    // 9. LN2 normalize-only -> d_out (single DRAM read pass)
    chan_norm_kernel<<<BATCH * NPOS / 256, 256>>>(
        outpre, out_norm_g, mean, rstd, out);
}

// round 16
// speedup vs baseline: 1.1525x; 1.1525x over previous
#include <cuda_runtime.h>
#include <cuda_fp16.h>
#include <math_constants.h>
#include <cstdint>

#define BATCH 16
#define CDIM  512
#define NPOS  4096      // 64*64
#define O3    1536      // 3*HID
#define HID   512
#define HEADS 8
#define DH    64
#define EPSV  1e-5f
#define QSCALE 0.125f   // DH^-0.5

typedef __half h16;

// ---------------- scratch (device globals; no allocations allowed) ---------
__device__ float g_mean [BATCH * NPOS];
__device__ float g_rstd [BATCH * NPOS];
__device__ h16   g_xt   [(size_t)BATCH * NPOS * CDIM];   // x normalized, channel-last fp16
__device__ float g_qkv  [(size_t)BATCH * O3   * NPOS];   // channel-major
__device__ float g_ctx  [BATCH * HEADS * DH * DH];
__device__ float g_kmx  [BATCH * HEADS * DH];            // k row max
__device__ float g_krz  [BATCH * HEADS * DH];            // k row 1/sum
__device__ h16   g_at   [(size_t)BATCH * NPOS * HID];    // attn out, channel-last fp16
__device__ float g_outpre[(size_t)BATCH * CDIM * NPOS];  // pre-final-LN, channel-major
__device__ h16   g_wq   [O3  * CDIM];
__device__ h16   g_wo   [HID * CDIM];

// ======================= mma.sync / cp.async helpers (sm_80+) ==============
__device__ __forceinline__ uint32_t smem_to_u32(const void* p) {
    uint32_t a;
    asm("{ .reg .u64 t; cvta.to.shared.u64 t, %1; cvt.u32.u64 %0, t; }"
        : "=r"(a) : "l"(p));
    return a;
}
__device__ __forceinline__ void ldsm_x4(uint32_t& r0, uint32_t& r1,
                                        uint32_t& r2, uint32_t& r3, uint32_t addr) {
    asm volatile("ldmatrix.sync.aligned.m8n8.x4.shared.b16 {%0,%1,%2,%3}, [%4];"
        : "=r"(r0), "=r"(r1), "=r"(r2), "=r"(r3) : "r"(addr));
}
__device__ __forceinline__ void mma16816(float* d, const uint32_t* a,
                                         uint32_t b0, uint32_t b1) {
    asm volatile(
        "mma.sync.aligned.m16n8k16.row.col.f32.f16.f16.f32 "
        "{%0,%1,%2,%3},{%4,%5,%6,%7},{%8,%9},{%0,%1,%2,%3};"
        : "+f"(d[0]), "+f"(d[1]), "+f"(d[2]), "+f"(d[3])
        : "r"(a[0]), "r"(a[1]), "r"(a[2]), "r"(a[3]), "r"(b0), "r"(b1));
}
__device__ __forceinline__ void cp_async16(uint32_t saddr, const void* gaddr) {
    asm volatile("cp.async.ca.shared.global [%0], [%1], 16;"
        :: "r"(saddr), "l"(gaddr));
}
#define CP_COMMIT()  asm volatile("cp.async.commit_group;" ::: "memory")
#define CP_WAIT(N)   asm volatile("cp.async.wait_group %0;" :: "n"(N) : "memory")

// ======================= single-product fp16 tensor-core GEMM ==============
// EMPIRICAL OPTIMUM (benched 1036.5us total): 256 thr, 4x2 warps, warp tile
// 32x64, 2-stage double buffer, KC=64, 73.7 KB smem, 2 CTAs/SM.
// C[b, bm+r, bn+c] = sum_k W[bm+r, k] * X[b, bn+c, k]  (+ bias[bm+r])
#define KC  64
#define LDT 72                              // KC + 8 pad; row stride 144 B
#define TILE_BYTES (128 * LDT * 2)          // 18432 B per tile
#define STAGE_BYTES (2 * TILE_BYTES)        // W, X  -> 36864 B
#define GEMM_SMEM  (2 * STAGE_BYTES)        // 73728 B (2 stages)

__global__ __launch_bounds__(256, 2) void gemm_mma(
    const h16* __restrict__ W, const h16* __restrict__ X,
    float* __restrict__ C, const float* __restrict__ bias, int M_total)
{
    extern __shared__ char sm[];
    uint32_t sbase = smem_to_u32(sm);

    int tid = threadIdx.x, wid = tid >> 5, lane = tid & 31;
    int b = blockIdx.z, bm = blockIdx.y * 128, bn = blockIdx.x * 128;
    int warp_m = (wid & 3) * 32;        // 4 warps along M
    int warp_n = (wid >> 2) * 64;       // 2 warps along N

    const uint4* gW = (const uint4*)W + (size_t)bm * 64;
    const uint4* gX = (const uint4*)X + ((size_t)b * NPOS + bn) * 64;

    float acc[2][8][4];
    #pragma unroll
    for (int mt = 0; mt < 2; mt++)
        #pragma unroll
        for (int nt = 0; nt < 8; nt++)
            #pragma unroll
            for (int f = 0; f < 4; f++) acc[mt][nt][f] = 0.f;

    auto load_stage = [&](int s, int kc) {
        uint32_t ub = sbase + (uint32_t)s * STAGE_BYTES;
        #pragma unroll
        for (int l = 0; l < 4; l++) {
            int i = l * 256 + tid;
            int row = i >> 3, c8 = i & 7;
            size_t go = (size_t)row * 64 + kc * 8 + c8;
            uint32_t so = ub + (uint32_t)(row * LDT + c8 * 8) * 2;
            cp_async16(so,              gW + go);
            cp_async16(so + TILE_BYTES, gX + go);
        }
    };

    load_stage(0, 0);
    CP_COMMIT();

    for (int kc = 0; kc < 8; kc++) {
        if (kc + 1 < 8) {
            load_stage((kc + 1) & 1, kc + 1);
            CP_COMMIT();
            CP_WAIT(1);
        } else {
            CP_WAIT(0);
        }
        __syncthreads();

        uint32_t ub = sbase + (uint32_t)(kc & 1) * STAGE_BYTES;
        uint32_t uW = ub;
        uint32_t uX = ub + TILE_BYTES;

        #pragma unroll
        for (int kk = 0; kk < 4; kk++) {
            uint32_t ah[2][4];
            #pragma unroll
            for (int mt = 0; mt < 2; mt++) {
                uint32_t off = 2 * (uint32_t)((warp_m + mt * 16 + (lane & 15)) * LDT
                                              + kk * 16 + (lane >> 4) * 8);
                ldsm_x4(ah[mt][0], ah[mt][1], ah[mt][2], ah[mt][3], uW + off);
            }
            #pragma unroll
            for (int nt2 = 0; nt2 < 4; nt2++) {
                uint32_t off = 2 * (uint32_t)((warp_n + nt2 * 16 + (lane & 15)) * LDT
                                              + kk * 16 + (lane >> 4) * 8);
                uint32_t b0, b1, b2, b3;
                ldsm_x4(b0, b1, b2, b3, uX + off);
                #pragma unroll
                for (int mt = 0; mt < 2; mt++) {
                    mma16816(acc[mt][nt2 * 2 + 0], ah[mt], b0, b2);
                    mma16816(acc[mt][nt2 * 2 + 1], ah[mt], b1, b3);
                }
            }
        }
        __syncthreads();
    }

    #pragma unroll
    for (int mt = 0; mt < 2; mt++) {
        int r0 = bm + warp_m + mt * 16 + (lane >> 2);
        float bb0 = bias ? bias[r0] : 0.f;
        float bb8 = bias ? bias[r0 + 8] : 0.f;
        #pragma unroll
        for (int nt = 0; nt < 8; nt++) {
            int col = bn + warp_n + nt * 8 + 2 * (lane & 3);
            float2 v0 = make_float2(acc[mt][nt][0] + bb0, acc[mt][nt][1] + bb0);
            float2 v1 = make_float2(acc[mt][nt][2] + bb8, acc[mt][nt][3] + bb8);
            *(float2*)&C[((size_t)b * M_total + r0    ) * NPOS + col] = v0;
            *(float2*)&C[((size_t)b * M_total + r0 + 8) * NPOS + col] = v1;
        }
    }
}

// ---------------- LN stats: mean/rstd over C per (b,p) ---------------------
__global__ __launch_bounds__(256) void ln_stats_kernel(
    const float* __restrict__ in, float* __restrict__ mean, float* __restrict__ rstd)
{
    int gid = blockIdx.x * 256 + threadIdx.x;
    int b = gid >> 12, p = gid & (NPOS - 1);
    const float* ip = in + (size_t)b * CDIM * NPOS + p;
    float s = 0.f, s2 = 0.f;
    #pragma unroll 8
    for (int c = 0; c < CDIM; c++) {
        float v = ip[(size_t)c * NPOS];
        s += v; s2 += v * v;
    }
    float m = s * (1.f / CDIM);
    float var = s2 * (1.f / CDIM) - m * m;
    mean[gid] = m;
    rstd[gid] = rsqrtf(var + EPSV);
}

// ---------------- normalize + transpose to channel-last fp16 ---------------
__global__ __launch_bounds__(256) void norm_transpose_kernel(
    const float* __restrict__ x, const float* __restrict__ g,
    const float* __restrict__ mean, const float* __restrict__ rstd,
    h16* __restrict__ xt)
{
    __shared__ float t[64][65];
    int b = blockIdx.z, c0 = blockIdx.y * 64, p0 = blockIdx.x * 64;
    int tid = threadIdx.x;
    #pragma unroll
    for (int l = 0; l < 16; l++) {
        int i = l * 256 + tid;
        int c = i >> 6, p = i & 63;
        float v = x[((size_t)b * CDIM + c0 + c) * NPOS + p0 + p];
        int sp = b * NPOS + p0 + p;
        t[p][c] = (v - mean[sp]) * rstd[sp] * g[c0 + c];
    }
    __syncthreads();
    #pragma unroll
    for (int l = 0; l < 16; l++) {
        int i = l * 256 + tid;
        int p = i >> 6, c = i & 63;
        size_t o = ((size_t)b * NPOS + p0 + p) * CDIM + c0 + c;
        xt[o] = __float2half(t[p][c]);
    }
}

// ---------------- fp32 -> fp16 convert (weights) ---------------------------
__global__ __launch_bounds__(256) void conv_fp16_kernel(
    const float* __restrict__ w, h16* __restrict__ h, int n)
{
    int i = blockIdx.x * 256 + threadIdx.x;
    if (i < n) h[i] = __float2half(w[i]);
}

// ---------------- warp reductions ------------------------------------------
__device__ __forceinline__ float warp_max(float v) {
    #pragma unroll
    for (int o = 16; o > 0; o >>= 1) v = fmaxf(v, __shfl_xor_sync(0xffffffffu, v, o));
    return v;
}
__device__ __forceinline__ float warp_sum(float v) {
    #pragma unroll
    for (int o = 16; o > 0; o >>= 1) v += __shfl_xor_sync(0xffffffffu, v, o);
    return v;
}

// ---------------- k row stats: max + 1/sum(exp) over n ---------------------
__global__ __launch_bounds__(256) void kstats_kernel(
    const float* __restrict__ qkv, float* __restrict__ kmx, float* __restrict__ krz)
{
    __shared__ float red[8];
    int row = blockIdx.x;                  // BATCH*HEADS*DH rows
    int i = row & (DH - 1);
    int m = (row >> 6) & (HEADS - 1);
    int b = row >> 9;
    const float* base = qkv + (size_t)b * O3 * NPOS + (size_t)(HID + m * DH + i) * NPOS;
    int t = threadIdx.x;
    int lane = t & 31, wid = t >> 5;

    float v[16];
    float mx = -CUDART_INF_F;
    #pragma unroll
    for (int u = 0; u < 16; u++) {
        v[u] = base[u * 256 + t];
        mx = fmaxf(mx, v[u]);
    }
    mx = warp_max(mx);
    if (lane == 0) red[wid] = mx;
    __syncthreads();
    mx = warp_max((lane < 8) ? red[lane] : -CUDART_INF_F);
    mx = __shfl_sync(0xffffffffu, mx, 0);

    float s = 0.f;
    #pragma unroll
    for (int u = 0; u < 16; u++) s += __expf(v[u] - mx);
    s = warp_sum(s);
    __syncthreads();
    if (lane == 0) red[wid] = s;
    __syncthreads();
    s = warp_sum((lane < 8) ? red[lane] : 0.f);
    s = __shfl_sync(0xffffffffu, s, 0);

    if (t == 0) { kmx[row] = mx; krz[row] = 1.f / s; }
}

// ---------------- zero (ctx, single launch) --------------------------------
__global__ __launch_bounds__(256) void zero_kernel(float* __restrict__ p, int n)
{
    int i = blockIdx.x * 256 + threadIdx.x;
    if (i < n) p[i] = 0.f;
}

// -------- context[b,m,i,j] = (1/Z_i) sum_n exp(k[i,n]-mx_i) * v[j,n] -------
#define NSPLIT 4
__global__ __launch_bounds__(256) void context_kernel(
    const float* __restrict__ qkv, const float* __restrict__ kmx,
    const float* __restrict__ krz, float* __restrict__ ctx)
{
    __shared__ float Ks[64][65];
    __shared__ float Vs[64][65];
    int bm = blockIdx.x;
    int m = bm & (HEADS - 1);
    int b = bm >> 3;
    const float* kbase = qkv + (size_t)b * O3 * NPOS + (size_t)(HID     + m * DH) * NPOS;
    const float* vbase = qkv + (size_t)b * O3 * NPOS + (size_t)(2 * HID + m * DH) * NPOS;
    int tid = threadIdx.x;
    int ti = tid & 15, tj = tid >> 4;

    float acc[4][4];
    #pragma unroll
    for (int a = 0; a < 4; a++)
        #pragma unroll
        for (int c = 0; c < 4; c++) acc[a][c] = 0.f;

    int nsplit = NPOS / NSPLIT;
    int nstart = blockIdx.y * nsplit;
    for (int nc = 0; nc < nsplit; nc += 64) {
        int nb = nstart + nc;
        #pragma unroll
        for (int l = 0; l < 16; l++) {
            int idx = l * 256 + tid;
            int i = idx >> 6, nn = idx & 63;
            Ks[nn][i] = __expf(kbase[(size_t)i * NPOS + nb + nn] - kmx[bm * DH + i]);
            Vs[nn][i] = vbase[(size_t)i * NPOS + nb + nn];
        }
        __syncthreads();
        #pragma unroll 8
        for (int nn = 0; nn < 64; nn++) {
            float ka[4], vb[4];
            #pragma unroll
            for (int a = 0; a < 4; a++) ka[a] = Ks[nn][ti * 4 + a];
            #pragma unroll
            for (int c = 0; c < 4; c++) vb[c] = Vs[nn][tj * 4 + c];
            #pragma unroll
            for (int a = 0; a < 4; a++)
                #pragma unroll
                for (int c = 0; c < 4; c++) acc[a][c] += ka[a] * vb[c];
        }
        __syncthreads();
    }
    #pragma unroll
    for (int a = 0; a < 4; a++) {
        float rz = krz[bm * DH + ti * 4 + a];
        #pragma unroll
        for (int c = 0; c < 4; c++)
            atomicAdd(&ctx[(size_t)bm * DH * DH + (ti * 4 + a) * DH + (tj * 4 + c)],
                      acc[a][c] * rz);
    }
}

// -------- attn_out -> channel-last fp16, with INLINE q softmax -------------
__global__ __launch_bounds__(128) void attnout_kernel(
    const float* __restrict__ qkv, const float* __restrict__ ctx,
    h16* __restrict__ at)
{
    __shared__ float cs[DH][DH];        // 16 KB
    __shared__ float stage[128][64];    // 32 KB
    int bm = blockIdx.y;
    int m = bm & (HEADS - 1);
    int b = bm >> 3;
    const float* qbase = qkv + (size_t)b * O3 * NPOS + (size_t)(m * DH) * NPOS;
    int tid = threadIdx.x;

    #pragma unroll
    for (int l = 0; l < 32; l++)
        ((float*)cs)[l * 128 + tid] = ctx[(size_t)bm * DH * DH + l * 128 + tid];
    __syncthreads();

    int n0 = blockIdx.x * 128;
    int n = n0 + tid;

    float v[DH];
    float mx = -CUDART_INF_F;
    #pragma unroll
    for (int i = 0; i < DH; i++) {
        v[i] = qbase[(size_t)i * NPOS + n];
        mx = fmaxf(mx, v[i]);
    }
    float s = 0.f;
    #pragma unroll
    for (int i = 0; i < DH; i++) { v[i] = __expf(v[i] - mx); s += v[i]; }
    float r = QSCALE / s;

    float accj[DH];
    #pragma unroll
    for (int j = 0; j < DH; j++) accj[j] = 0.f;

    #pragma unroll 2
    for (int i = 0; i < DH; i++) {
        float qv = v[i];
        const float4* rowp = (const float4*)cs[i];
        #pragma unroll
        for (int j4 = 0; j4 < 16; j4++) {
            float4 c4 = rowp[j4];
            accj[j4 * 4 + 0] += c4.x * qv;
            accj[j4 * 4 + 1] += c4.y * qv;
            accj[j4 * 4 + 2] += c4.z * qv;
            accj[j4 * 4 + 3] += c4.w * qv;
        }
    }
    #pragma unroll
    for (int j = 0; j < DH; j++) stage[tid][(j + tid) & 63] = accj[j] * r;
    __syncthreads();

    #pragma unroll
    for (int l = 0; l < 64; l++) {
        int idx = l * 128 + tid;
        int p = idx >> 6, j = idx & 63;
        size_t o = ((size_t)b * NPOS + n0 + p) * HID + m * DH + j;
        at[o] = __float2half(stage[p][(j + p) & 63]);
    }
}

// ---------------- final channel layernorm (channel-major, 2-pass) ----------
__global__ __launch_bounds__(256) void chan_ln_kernel(
    const float* __restrict__ in, const float* __restrict__ g,
    float* __restrict__ out)
{
    int gid = blockIdx.x * 256 + threadIdx.x;
    int b = gid >> 12;
    int p = gid & (NPOS - 1);
    const float* ip = in  + (size_t)b * CDIM * NPOS + p;
    float*       op = out + (size_t)b * CDIM * NPOS + p;

    float s = 0.f, s2 = 0.f;
    #pragma unroll 8
    for (int c = 0; c < CDIM; c++) {
        float v = ip[(size_t)c * NPOS];
        s += v; s2 += v * v;
    }
    float mean = s * (1.f / CDIM);
    float var = s2 * (1.f / CDIM) - mean * mean;
    float rstd = rsqrtf(var + EPSV);

    #pragma unroll 8
    for (int c = 0; c < CDIM; c++) {
        float v = ip[(size_t)c * NPOS];
        op[(size_t)c * NPOS] = (v - mean) * rstd * g[c];
    }
}

// ---------------- launch ---------------------------------------------------
extern "C" void kernel_launch(void* const* d_in, const int* in_sizes, int n_in,
                              void* d_out, int out_size)
{
    const float* x          = (const float*)d_in[0];
    const float* norm_g     = (const float*)d_in[1];
    const float* qkv_w      = (const float*)d_in[2];
    const float* out_w      = (const float*)d_in[3];
    const float* out_b      = (const float*)d_in[4];
    const float* out_norm_g = (const float*)d_in[5];
    float* out = (float*)d_out;

    float *mean, *rstd, *qkv, *ctx, *kmx, *krz, *outpre;
    h16 *xt, *at, *wq, *wo;
    cudaGetSymbolAddress((void**)&mean,   g_mean);
    cudaGetSymbolAddress((void**)&rstd,   g_rstd);
    cudaGetSymbolAddress((void**)&xt,     g_xt);
    cudaGetSymbolAddress((void**)&qkv,    g_qkv);
    cudaGetSymbolAddress((void**)&ctx,    g_ctx);
    cudaGetSymbolAddress((void**)&kmx,    g_kmx);
    cudaGetSymbolAddress((void**)&krz,    g_krz);
    cudaGetSymbolAddress((void**)&at,     g_at);
    cudaGetSymbolAddress((void**)&outpre, g_outpre);
    cudaGetSymbolAddress((void**)&wq,     g_wq);
    cudaGetSymbolAddress((void**)&wo,     g_wo);

    cudaFuncSetAttribute(gemm_mma, cudaFuncAttributeMaxDynamicSharedMemorySize,
                         GEMM_SMEM);

    // 1. LN1: stats + normalize-transpose (x -> xt fp16, channel-last)
    ln_stats_kernel<<<BATCH * NPOS / 256, 256>>>(x, mean, rstd);
    norm_transpose_kernel<<<dim3(NPOS / 64, CDIM / 64, BATCH), 256>>>(
        x, norm_g, mean, rstd, xt);

    // 2. weight converts (single fp16)
    conv_fp16_kernel<<<(O3 * CDIM) / 256, 256>>>(qkv_w, wq, O3 * CDIM);
    conv_fp16_kernel<<<(HID * CDIM) / 256, 256>>>(out_w, wo, HID * CDIM);

    // 3. qkv GEMM (empirical-optimum config)
    gemm_mma<<<dim3(NPOS / 128, O3 / 128, BATCH), 256, GEMM_SMEM>>>(
        wq, xt, qkv, nullptr, O3);

    // 4. k row stats (softmax_k folded into context)
    kstats_kernel<<<BATCH * HEADS * DH, 256>>>(qkv, kmx, krz);

    // 5. context = softmax(k) @ v^T  (exp applied inline, 1/Z in epilogue)
    int ctx_n = BATCH * HEADS * DH * DH;
    zero_kernel<<<(ctx_n + 255) / 256, 256>>>(ctx, ctx_n);
    context_kernel<<<dim3(BATCH * HEADS, NSPLIT), 256>>>(qkv, kmx, krz, ctx);

    // 6. attn out (inline q softmax) -> channel-last fp16
    attnout_kernel<<<dim3(NPOS / 128, BATCH * HEADS), 128>>>(qkv, ctx, at);

    // 7. out projection + bias -> outpre (channel-major)
    gemm_mma<<<dim3(NPOS / 128, HID / 128, BATCH), 256, GEMM_SMEM>>>(
        wo, at, outpre, out_b, HID);

    // 8. final channel LN -> d_out
    chan_ln_kernel<<<BATCH * NPOS / 256, 256>>>(outpre, out_norm_g, out);
}

// round 17
// speedup vs baseline: 1.1570x; 1.0039x over previous
#include <cuda_runtime.h>
#include <cuda_fp16.h>
#include <math_constants.h>
#include <cstdint>

#define BATCH 16
#define CDIM  512
#define NPOS  4096      // 64*64
#define O3    1536      // 3*HID
#define HID   512
#define HEADS 8
#define DH    64
#define EPSV  1e-5f
#define QSCALE 0.125f   // DH^-0.5

typedef __half h16;

// ---------------- scratch (device globals; no allocations allowed) ---------
__device__ float g_mean [BATCH * NPOS];
__device__ float g_rstd [BATCH * NPOS];
__device__ h16   g_xt   [(size_t)BATCH * NPOS * CDIM];   // x normalized, channel-last fp16
__device__ float g_qkv  [(size_t)BATCH * O3   * NPOS];   // channel-major
__device__ float g_ctx  [BATCH * HEADS * DH * DH];
__device__ float g_kmx  [BATCH * HEADS * DH];            // k row max
__device__ float g_krz  [BATCH * HEADS * DH];            // k row 1/sum
__device__ h16   g_at   [(size_t)BATCH * NPOS * HID];    // attn out, channel-last fp16
__device__ float g_outpre[(size_t)BATCH * CDIM * NPOS];  // pre-final-LN, channel-major
__device__ h16   g_wq   [O3  * CDIM];
__device__ h16   g_wo   [HID * CDIM];

// ======================= mma.sync / cp.async helpers (sm_80+) ==============
__device__ __forceinline__ uint32_t smem_to_u32(const void* p) {
    uint32_t a;
    asm("{ .reg .u64 t; cvta.to.shared.u64 t, %1; cvt.u32.u64 %0, t; }"
        : "=r"(a) : "l"(p));
    return a;
}
__device__ __forceinline__ void ldsm_x4(uint32_t& r0, uint32_t& r1,
                                        uint32_t& r2, uint32_t& r3, uint32_t addr) {
    asm volatile("ldmatrix.sync.aligned.m8n8.x4.shared.b16 {%0,%1,%2,%3}, [%4];"
        : "=r"(r0), "=r"(r1), "=r"(r2), "=r"(r3) : "r"(addr));
}
__device__ __forceinline__ void mma16816(float* d, const uint32_t* a,
                                         uint32_t b0, uint32_t b1) {
    asm volatile(
        "mma.sync.aligned.m16n8k16.row.col.f32.f16.f16.f32 "
        "{%0,%1,%2,%3},{%4,%5,%6,%7},{%8,%9},{%0,%1,%2,%3};"
        : "+f"(d[0]), "+f"(d[1]), "+f"(d[2]), "+f"(d[3])
        : "r"(a[0]), "r"(a[1]), "r"(a[2]), "r"(a[3]), "r"(b0), "r"(b1));
}
__device__ __forceinline__ void cp_async16(uint32_t saddr, const void* gaddr) {
    asm volatile("cp.async.ca.shared.global [%0], [%1], 16;"
        :: "r"(saddr), "l"(gaddr));
}
#define CP_COMMIT()  asm volatile("cp.async.commit_group;" ::: "memory")
#define CP_WAIT(N)   asm volatile("cp.async.wait_group %0;" :: "n"(N) : "memory")

// ======================= single-product fp16 tensor-core GEMM ==============
// EMPIRICAL OPTIMUM config (benched 1036.3us total): 256 thr, 4x2 warps,
// warp tile 32x64, 2-stage double buffer, KC=64, 73.7 KB smem, 2 CTAs/SM.
// Refinement: ONE barrier per K-chunk (prefetch issued after the barrier;
// the stage it overwrites was consumed in iter kc-1, provably complete here).
// C[b, bm+r, bn+c] = sum_k W[bm+r, k] * X[b, bn+c, k]  (+ bias[bm+r])
#define KC  64
#define LDT 72                              // KC + 8 pad; row stride 144 B
#define TILE_BYTES (128 * LDT * 2)          // 18432 B per tile
#define STAGE_BYTES (2 * TILE_BYTES)        // W, X  -> 36864 B
#define GEMM_SMEM  (2 * STAGE_BYTES)        // 73728 B (2 stages)

__global__ __launch_bounds__(256, 2) void gemm_mma(
    const h16* __restrict__ W, const h16* __restrict__ X,
    float* __restrict__ C, const float* __restrict__ bias, int M_total)
{
    extern __shared__ char sm[];
    uint32_t sbase = smem_to_u32(sm);

    int tid = threadIdx.x, wid = tid >> 5, lane = tid & 31;
    int b = blockIdx.z, bm = blockIdx.y * 128, bn = blockIdx.x * 128;
    int warp_m = (wid & 3) * 32;        // 4 warps along M
    int warp_n = (wid >> 2) * 64;       // 2 warps along N

    const uint4* gW = (const uint4*)W + (size_t)bm * 64;
    const uint4* gX = (const uint4*)X + ((size_t)b * NPOS + bn) * 64;

    float acc[2][8][4];
    #pragma unroll
    for (int mt = 0; mt < 2; mt++)
        #pragma unroll
        for (int nt = 0; nt < 8; nt++)
            #pragma unroll
            for (int f = 0; f < 4; f++) acc[mt][nt][f] = 0.f;

    auto load_stage = [&](int s, int kc) {
        uint32_t ub = sbase + (uint32_t)s * STAGE_BYTES;
        #pragma unroll
        for (int l = 0; l < 4; l++) {
            int i = l * 256 + tid;
            int row = i >> 3, c8 = i & 7;
            size_t go = (size_t)row * 64 + kc * 8 + c8;
            uint32_t so = ub + (uint32_t)(row * LDT + c8 * 8) * 2;
            cp_async16(so,              gW + go);
            cp_async16(so + TILE_BYTES, gX + go);
        }
    };

    load_stage(0, 0);
    CP_COMMIT();

    for (int kc = 0; kc < 8; kc++) {
        CP_WAIT(0);                 // drain prefetch of chunk kc
        __syncthreads();            // data visible; iter kc-1 compute complete
        if (kc + 1 < 8) {           // prefetch kc+1 into the stage freed at kc-1
            load_stage((kc + 1) & 1, kc + 1);
            CP_COMMIT();
        }

        uint32_t ub = sbase + (uint32_t)(kc & 1) * STAGE_BYTES;
        uint32_t uW = ub;
        uint32_t uX = ub + TILE_BYTES;

        #pragma unroll
        for (int kk = 0; kk < 4; kk++) {
            uint32_t ah[2][4];
            #pragma unroll
            for (int mt = 0; mt < 2; mt++) {
                uint32_t off = 2 * (uint32_t)((warp_m + mt * 16 + (lane & 15)) * LDT
                                              + kk * 16 + (lane >> 4) * 8);
                ldsm_x4(ah[mt][0], ah[mt][1], ah[mt][2], ah[mt][3], uW + off);
            }
            #pragma unroll
            for (int nt2 = 0; nt2 < 4; nt2++) {
                uint32_t off = 2 * (uint32_t)((warp_n + nt2 * 16 + (lane & 15)) * LDT
                                              + kk * 16 + (lane >> 4) * 8);
                uint32_t b0, b1, b2, b3;
                ldsm_x4(b0, b1, b2, b3, uX + off);
                #pragma unroll
                for (int mt = 0; mt < 2; mt++) {
                    mma16816(acc[mt][nt2 * 2 + 0], ah[mt], b0, b2);
                    mma16816(acc[mt][nt2 * 2 + 1], ah[mt], b1, b3);
                }
            }
        }
    }

    #pragma unroll
    for (int mt = 0; mt < 2; mt++) {
        int r0 = bm + warp_m + mt * 16 + (lane >> 2);
        float bb0 = bias ? bias[r0] : 0.f;
        float bb8 = bias ? bias[r0 + 8] : 0.f;
        #pragma unroll
        for (int nt = 0; nt < 8; nt++) {
            int col = bn + warp_n + nt * 8 + 2 * (lane & 3);
            float2 v0 = make_float2(acc[mt][nt][0] + bb0, acc[mt][nt][1] + bb0);
            float2 v1 = make_float2(acc[mt][nt][2] + bb8, acc[mt][nt][3] + bb8);
            *(float2*)&C[((size_t)b * M_total + r0    ) * NPOS + col] = v0;
            *(float2*)&C[((size_t)b * M_total + r0 + 8) * NPOS + col] = v1;
        }
    }
}

// ---------------- LN stats: mean/rstd over C per (b,p) ---------------------
__global__ __launch_bounds__(256) void ln_stats_kernel(
    const float* __restrict__ in, float* __restrict__ mean, float* __restrict__ rstd)
{
    int gid = blockIdx.x * 256 + threadIdx.x;
    int b = gid >> 12, p = gid & (NPOS - 1);
    const float* ip = in + (size_t)b * CDIM * NPOS + p;
    float s = 0.f, s2 = 0.f;
    #pragma unroll 8
    for (int c = 0; c < CDIM; c++) {
        float v = ip[(size_t)c * NPOS];
        s += v; s2 += v * v;
    }
    float m = s * (1.f / CDIM);
    float var = s2 * (1.f / CDIM) - m * m;
    mean[gid] = m;
    rstd[gid] = rsqrtf(var + EPSV);
}

// ---------------- normalize + transpose to channel-last fp16 ---------------
__global__ __launch_bounds__(256) void norm_transpose_kernel(
    const float* __restrict__ x, const float* __restrict__ g,
    const float* __restrict__ mean, const float* __restrict__ rstd,
    h16* __restrict__ xt)
{
    __shared__ float t[64][65];
    int b = blockIdx.z, c0 = blockIdx.y * 64, p0 = blockIdx.x * 64;
    int tid = threadIdx.x;
    #pragma unroll
    for (int l = 0; l < 16; l++) {
        int i = l * 256 + tid;
        int c = i >> 6, p = i & 63;
        float v = x[((size_t)b * CDIM + c0 + c) * NPOS + p0 + p];
        int sp = b * NPOS + p0 + p;
        t[p][c] = (v - mean[sp]) * rstd[sp] * g[c0 + c];
    }
    __syncthreads();
    #pragma unroll
    for (int l = 0; l < 16; l++) {
        int i = l * 256 + tid;
        int p = i >> 6, c = i & 63;
        size_t o = ((size_t)b * NPOS + p0 + p) * CDIM + c0 + c;
        xt[o] = __float2half(t[p][c]);
    }
}

// ---------------- fp32 -> fp16 convert (weights) ---------------------------
__global__ __launch_bounds__(256) void conv_fp16_kernel(
    const float* __restrict__ w, h16* __restrict__ h, int n)
{
    int i = blockIdx.x * 256 + threadIdx.x;
    if (i < n) h[i] = __float2half(w[i]);
}

// ---------------- warp reductions ------------------------------------------
__device__ __forceinline__ float warp_max(float v) {
    #pragma unroll
    for (int o = 16; o > 0; o >>= 1) v = fmaxf(v, __shfl_xor_sync(0xffffffffu, v, o));
    return v;
}
__device__ __forceinline__ float warp_sum(float v) {
    #pragma unroll
    for (int o = 16; o > 0; o >>= 1) v += __shfl_xor_sync(0xffffffffu, v, o);
    return v;
}

// ---------------- k row stats: max + 1/sum(exp) over n ---------------------
__global__ __launch_bounds__(256) void kstats_kernel(
    const float* __restrict__ qkv, float* __restrict__ kmx, float* __restrict__ krz)
{
    __shared__ float red[8];
    int row = blockIdx.x;                  // BATCH*HEADS*DH rows
    int i = row & (DH - 1);
    int m = (row >> 6) & (HEADS - 1);
    int b = row >> 9;
    const float* base = qkv + (size_t)b * O3 * NPOS + (size_t)(HID + m * DH + i) * NPOS;
    int t = threadIdx.x;
    int lane = t & 31, wid = t >> 5;

    float v[16];
    float mx = -CUDART_INF_F;
    #pragma unroll
    for (int u = 0; u < 16; u++) {
        v[u] = base[u * 256 + t];
        mx = fmaxf(mx, v[u]);
    }
    mx = warp_max(mx);
    if (lane == 0) red[wid] = mx;
    __syncthreads();
    mx = warp_max((lane < 8) ? red[lane] : -CUDART_INF_F);
    mx = __shfl_sync(0xffffffffu, mx, 0);

    float s = 0.f;
    #pragma unroll
    for (int u = 0; u < 16; u++) s += __expf(v[u] - mx);
    s = warp_sum(s);
    __syncthreads();
    if (lane == 0) red[wid] = s;
    __syncthreads();
    s = warp_sum((lane < 8) ? red[lane] : 0.f);
    s = __shfl_sync(0xffffffffu, s, 0);

    if (t == 0) { kmx[row] = mx; krz[row] = 1.f / s; }
}

// ---------------- zero (ctx, single launch) --------------------------------
__global__ __launch_bounds__(256) void zero_kernel(float* __restrict__ p, int n)
{
    int i = blockIdx.x * 256 + threadIdx.x;
    if (i < n) p[i] = 0.f;
}

// -------- context[b,m,i,j] = (1/Z_i) sum_n exp(k[i,n]-mx_i) * v[j,n] -------
#define NSPLIT 4
__global__ __launch_bounds__(256) void context_kernel(
    const float* __restrict__ qkv, const float* __restrict__ kmx,
    const float* __restrict__ krz, float* __restrict__ ctx)
{
    __shared__ float Ks[64][65];
    __shared__ float Vs[64][65];
    int bm = blockIdx.x;
    int m = bm & (HEADS - 1);
    int b = bm >> 3;
    const float* kbase = qkv + (size_t)b * O3 * NPOS + (size_t)(HID     + m * DH) * NPOS;
    const float* vbase = qkv + (size_t)b * O3 * NPOS + (size_t)(2 * HID + m * DH) * NPOS;
    int tid = threadIdx.x;
    int ti = tid & 15, tj = tid >> 4;

    float acc[4][4];
    #pragma unroll
    for (int a = 0; a < 4; a++)
        #pragma unroll
        for (int c = 0; c < 4; c++) acc[a][c] = 0.f;

    int nsplit = NPOS / NSPLIT;
    int nstart = blockIdx.y * nsplit;
    for (int nc = 0; nc < nsplit; nc += 64) {
        int nb = nstart + nc;
        #pragma unroll
        for (int l = 0; l < 16; l++) {
            int idx = l * 256 + tid;
            int i = idx >> 6, nn = idx & 63;
            Ks[nn][i] = __expf(kbase[(size_t)i * NPOS + nb + nn] - kmx[bm * DH + i]);
            Vs[nn][i] = vbase[(size_t)i * NPOS + nb + nn];
        }
        __syncthreads();
        #pragma unroll 8
        for (int nn = 0; nn < 64; nn++) {
            float ka[4], vb[4];
            #pragma unroll
            for (int a = 0; a < 4; a++) ka[a] = Ks[nn][ti * 4 + a];
            #pragma unroll
            for (int c = 0; c < 4; c++) vb[c] = Vs[nn][tj * 4 + c];
            #pragma unroll
            for (int a = 0; a < 4; a++)
                #pragma unroll
                for (int c = 0; c < 4; c++) acc[a][c] += ka[a] * vb[c];
        }
        __syncthreads();
    }
    #pragma unroll
    for (int a = 0; a < 4; a++) {
        float rz = krz[bm * DH + ti * 4 + a];
        #pragma unroll
        for (int c = 0; c < 4; c++)
            atomicAdd(&ctx[(size_t)bm * DH * DH + (ti * 4 + a) * DH + (tj * 4 + c)],
                      acc[a][c] * rz);
    }
}

// -------- attn_out -> channel-last fp16, with INLINE q softmax -------------
__global__ __launch_bounds__(128) void attnout_kernel(
    const float* __restrict__ qkv, const float* __restrict__ ctx,
    h16* __restrict__ at)
{
    __shared__ float cs[DH][DH];        // 16 KB
    __shared__ float stage[128][64];    // 32 KB
    int bm = blockIdx.y;
    int m = bm & (HEADS - 1);
    int b = bm >> 3;
    const float* qbase = qkv + (size_t)b * O3 * NPOS + (size_t)(m * DH) * NPOS;
    int tid = threadIdx.x;

    #pragma unroll
    for (int l = 0; l < 32; l++)
        ((float*)cs)[l * 128 + tid] = ctx[(size_t)bm * DH * DH + l * 128 + tid];
    __syncthreads();

    int n0 = blockIdx.x * 128;
    int n = n0 + tid;

    float v[DH];
    float mx = -CUDART_INF_F;
    #pragma unroll
    for (int i = 0; i < DH; i++) {
        v[i] = qbase[(size_t)i * NPOS + n];
        mx = fmaxf(mx, v[i]);
    }
    float s = 0.f;
    #pragma unroll
    for (int i = 0; i < DH; i++) { v[i] = __expf(v[i] - mx); s += v[i]; }
    float r = QSCALE / s;

    float accj[DH];
    #pragma unroll
    for (int j = 0; j < DH; j++) accj[j] = 0.f;

    #pragma unroll 2
    for (int i = 0; i < DH; i++) {
        float qv = v[i];
        const float4* rowp = (const float4*)cs[i];
        #pragma unroll
        for (int j4 = 0; j4 < 16; j4++) {
            float4 c4 = rowp[j4];
            accj[j4 * 4 + 0] += c4.x * qv;
            accj[j4 * 4 + 1] += c4.y * qv;
            accj[j4 * 4 + 2] += c4.z * qv;
            accj[j4 * 4 + 3] += c4.w * qv;
        }
    }
    #pragma unroll
    for (int j = 0; j < DH; j++) stage[tid][(j + tid) & 63] = accj[j] * r;
    __syncthreads();

    #pragma unroll
    for (int l = 0; l < 64; l++) {
        int idx = l * 128 + tid;
        int p = idx >> 6, j = idx & 63;
        size_t o = ((size_t)b * NPOS + n0 + p) * HID + m * DH + j;
        at[o] = __float2half(stage[p][(j + p) & 63]);
    }
}

// ---------------- final channel layernorm (channel-major, 2-pass) ----------
__global__ __launch_bounds__(256) void chan_ln_kernel(
    const float* __restrict__ in, const float* __restrict__ g,
    float* __restrict__ out)
{
    int gid = blockIdx.x * 256 + threadIdx.x;
    int b = gid >> 12;
    int p = gid & (NPOS - 1);
    const float* ip = in  + (size_t)b * CDIM * NPOS + p;
    float*       op = out + (size_t)b * CDIM * NPOS + p;

    float s = 0.f, s2 = 0.f;
    #pragma unroll 8
    for (int c = 0; c < CDIM; c++) {
        float v = ip[(size_t)c * NPOS];
        s += v; s2 += v * v;
    }
    float mean = s * (1.f / CDIM);
    float var = s2 * (1.f / CDIM) - mean * mean;
    float rstd = rsqrtf(var + EPSV);

    #pragma unroll 8
    for (int c = 0; c < CDIM; c++) {
        float v = ip[(size_t)c * NPOS];
        op[(size_t)c * NPOS] = (v - mean) * rstd * g[c];
    }
}

// ---------------- launch ---------------------------------------------------
extern "C" void kernel_launch(void* const* d_in, const int* in_sizes, int n_in,
                              void* d_out, int out_size)
{
    const float* x          = (const float*)d_in[0];
    const float* norm_g     = (const float*)d_in[1];
    const float* qkv_w      = (const float*)d_in[2];
    const float* out_w      = (const float*)d_in[3];
    const float* out_b      = (const float*)d_in[4];
    const float* out_norm_g = (const float*)d_in[5];
    float* out = (float*)d_out;

    float *mean, *rstd, *qkv, *ctx, *kmx, *krz, *outpre;
    h16 *xt, *at, *wq, *wo;
    cudaGetSymbolAddress((void**)&mean,   g_mean);
    cudaGetSymbolAddress((void**)&rstd,   g_rstd);
    cudaGetSymbolAddress((void**)&xt,     g_xt);
    cudaGetSymbolAddress((void**)&qkv,    g_qkv);
    cudaGetSymbolAddress((void**)&ctx,    g_ctx);
    cudaGetSymbolAddress((void**)&kmx,    g_kmx);
    cudaGetSymbolAddress((void**)&krz,    g_krz);
    cudaGetSymbolAddress((void**)&at,     g_at);
    cudaGetSymbolAddress((void**)&outpre, g_outpre);
    cudaGetSymbolAddress((void**)&wq,     g_wq);
    cudaGetSymbolAddress((void**)&wo,     g_wo);

    cudaFuncSetAttribute(gemm_mma, cudaFuncAttributeMaxDynamicSharedMemorySize,
                         GEMM_SMEM);

    // 1. LN1: stats + normalize-transpose (x -> xt fp16, channel-last)
    ln_stats_kernel<<<BATCH * NPOS / 256, 256>>>(x, mean, rstd);
    norm_transpose_kernel<<<dim3(NPOS / 64, CDIM / 64, BATCH), 256>>>(
        x, norm_g, mean, rstd, xt);

    // 2. weight converts (single fp16)
    conv_fp16_kernel<<<(O3 * CDIM) / 256, 256>>>(qkv_w, wq, O3 * CDIM);
    conv_fp16_kernel<<<(HID * CDIM) / 256, 256>>>(out_w, wo, HID * CDIM);

    // 3. qkv GEMM (optimum config, single-barrier mainloop)
    gemm_mma<<<dim3(NPOS / 128, O3 / 128, BATCH), 256, GEMM_SMEM>>>(
        wq, xt, qkv, nullptr, O3);

    // 4. k row stats (softmax_k folded into context)
    kstats_kernel<<<BATCH * HEADS * DH, 256>>>(qkv, kmx, krz);

    // 5. context = softmax(k) @ v^T  (exp applied inline, 1/Z in epilogue)
    int ctx_n = BATCH * HEADS * DH * DH;
    zero_kernel<<<(ctx_n + 255) / 256, 256>>>(ctx, ctx_n);
    context_kernel<<<dim3(BATCH * HEADS, NSPLIT), 256>>>(qkv, kmx, krz, ctx);

    // 6. attn out (inline q softmax) -> channel-last fp16
    attnout_kernel<<<dim3(NPOS / 128, BATCH * HEADS), 128>>>(qkv, ctx, at);

    // 7. out projection + bias -> outpre (channel-major)
    gemm_mma<<<dim3(NPOS / 128, HID / 128, BATCH), 256, GEMM_SMEM>>>(
        wo, at, outpre, out_b, HID);

    // 8. final channel LN -> d_out
    chan_ln_kernel<<<BATCH * NPOS / 256, 256>>>(outpre, out_norm_g, out);
}